// round 3
// baseline (speedup 1.0000x reference)
#include <cuda_runtime.h>
#include <cuda_bf16.h>
#include <math.h>

// Problem constants (fixed by the dataset)
#define MAXN 50000
#define MAXE 800000
#define FDIM 128
#define HDIM 256
#define LDIM 64
#define NGRAPH 500

// ---------------- static scratch (no allocs allowed) ----------------
__device__ float g_bufA[(size_t)MAXN * HDIM];
__device__ float g_bufB[(size_t)MAXN * HDIM];
__device__ int   g_counts[MAXN];
__device__ int   g_rowptr[MAXN + 1];
__device__ int   g_wpos[MAXN];
__device__ int   g_csr[MAXE];
__device__ float g_wcsr[MAXE];       // dinv[src] per CSR slot
__device__ float g_dinv[MAXN];
__device__ float g_sums[NGRAPH * HDIM];
__device__ float g_gcnt[NGRAPH];

// ---------------- degree / CSR build ----------------
__global__ void k_count(const int* __restrict__ dst, int E) {
    int e = blockIdx.x * blockDim.x + threadIdx.x;
    if (e < E) atomicAdd(&g_counts[dst[e]], 1);
}

__global__ void k_dinv(int N) {
    int i = blockIdx.x * blockDim.x + threadIdx.x;
    if (i < N) g_dinv[i] = rsqrtf((float)g_counts[i] + 1.0f);  // +1 self-loop
}

// single-block exclusive scan of g_counts -> g_rowptr (+ copy to g_wpos)
__global__ void k_scan(int N, int E) {
    __shared__ int sdata[1024];
    __shared__ int carry_s;
    int tid = threadIdx.x;
    if (tid == 0) carry_s = 0;
    __syncthreads();
    for (int base = 0; base < N; base += 1024) {
        int i = base + tid;
        int v = (i < N) ? g_counts[i] : 0;
        sdata[tid] = v;
        __syncthreads();
        #pragma unroll
        for (int off = 1; off < 1024; off <<= 1) {
            int t2 = (tid >= off) ? sdata[tid - off] : 0;
            __syncthreads();
            sdata[tid] += t2;
            __syncthreads();
        }
        int incl = sdata[tid];
        int excl = incl - v + carry_s;
        if (i < N) { g_rowptr[i] = excl; g_wpos[i] = excl; }
        __syncthreads();
        if (tid == 1023) carry_s += incl;
        __syncthreads();
    }
    if (tid == 0) g_rowptr[N] = E;
}

// fill CSR with src index AND precomputed weight dinv[src]
__global__ void k_fill(const int* __restrict__ src, const int* __restrict__ dst, int E) {
    int e = blockIdx.x * blockDim.x + threadIdx.x;
    if (e < E) {
        int s = src[e];
        int p = atomicAdd(&g_wpos[dst[e]], 1);
        g_csr[p]  = s;
        g_wcsr[p] = g_dinv[s];
    }
}

// ---------------- GCN aggregation: warp-per-node, float4 vectorized --------
// out[d, :] = dinv[d] * ( dinv[d]*in[d,:] + sum_{s->d} dinv[s]*in[s,:] )
// V = number of float4 per lane (F/128). No block barriers; edge reads are
// lane-uniform broadcasts; row gathers fully coalesced.
template <int V>
__global__ void k_agg(const float* __restrict__ in, float* __restrict__ out, int N) {
    int warp = (blockIdx.x * blockDim.x + threadIdx.x) >> 5;
    if (warp >= N) return;
    int lane = threadIdx.x & 31;
    const int F = V * 128;
    int d = warp;
    float dv = g_dinv[d];

    float4 acc[V];
    const float4* selfrow = (const float4*)(in + (size_t)d * F) + lane;
    #pragma unroll
    for (int v = 0; v < V; v++) {
        float4 r = __ldg(selfrow + v * 32);
        acc[v] = make_float4(dv * r.x, dv * r.y, dv * r.z, dv * r.w);
    }

    int beg = g_rowptr[d], end = g_rowptr[d + 1];
    int   s_nx = 0; float w_nx = 0.0f;
    if (beg < end) { s_nx = __ldg(&g_csr[beg]); w_nx = __ldg(&g_wcsr[beg]); }
    for (int j = beg; j < end; j++) {
        int   s = s_nx;
        float w = w_nx;
        if (j + 1 < end) { s_nx = __ldg(&g_csr[j + 1]); w_nx = __ldg(&g_wcsr[j + 1]); }
        const float4* row = (const float4*)(in + (size_t)s * F) + lane;
        #pragma unroll
        for (int v = 0; v < V; v++) {
            float4 r = __ldg(row + v * 32);
            acc[v].x = fmaf(w, r.x, acc[v].x);
            acc[v].y = fmaf(w, r.y, acc[v].y);
            acc[v].z = fmaf(w, r.z, acc[v].z);
            acc[v].w = fmaf(w, r.w, acc[v].w);
        }
    }

    float4* orow = (float4*)(out + (size_t)d * F) + lane;
    #pragma unroll
    for (int v = 0; v < V; v++) {
        float4 o = make_float4(dv * acc[v].x, dv * acc[v].y, dv * acc[v].z, dv * acc[v].w);
        orow[v * 32] = o;
    }
}

// ---------------- SGEMM: C = relu(A[M,K] @ B[K,Ncols] + bias) -------------
#define BM 128
#define BN 128
#define BK 16
#define TM 8
#define TN 8

__global__ __launch_bounds__(256, 2)
void k_sgemm_bias_relu(const float* __restrict__ A, const float* __restrict__ B,
                       const float* __restrict__ bias, float* __restrict__ C,
                       int M, int K, int Ncols) {
    __shared__ float As[BK][BM];
    __shared__ float Bs[BK][BN];
    int tid = threadIdx.x;
    int block_row = blockIdx.y * BM;
    int block_col = blockIdx.x * BN;
    int tr = tid >> 4, tc = tid & 15;

    float acc[TM][TN];
    #pragma unroll
    for (int i = 0; i < TM; i++)
        #pragma unroll
        for (int j = 0; j < TN; j++) acc[i][j] = 0.0f;

    for (int k0 = 0; k0 < K; k0 += BK) {
        #pragma unroll
        for (int l = 0; l < 2; l++) {
            int idx = tid + l * 256;
            // A tile: 128 rows x 16 cols = 512 float4
            int m  = idx >> 2;
            int k4 = (idx & 3) * 4;
            int gm = block_row + m;
            float4 va = make_float4(0.f, 0.f, 0.f, 0.f);
            if (gm < M) va = __ldg((const float4*)(A + (size_t)gm * K + k0 + k4));
            As[k4 + 0][m] = va.x; As[k4 + 1][m] = va.y;
            As[k4 + 2][m] = va.z; As[k4 + 3][m] = va.w;
            // B tile: 16 rows x 128 cols = 512 float4
            int kk = idx >> 5;
            int n4 = (idx & 31) * 4;
            float4 vb = __ldg((const float4*)(B + (size_t)(k0 + kk) * Ncols + block_col + n4));
            *((float4*)&Bs[kk][n4]) = vb;
        }
        __syncthreads();
        #pragma unroll
        for (int k = 0; k < BK; k++) {
            float a[TM], b[TN];
            #pragma unroll
            for (int i = 0; i < TM; i++) a[i] = As[k][tr * TM + i];
            #pragma unroll
            for (int j = 0; j < TN; j++) b[j] = Bs[k][tc * TN + j];
            #pragma unroll
            for (int i = 0; i < TM; i++)
                #pragma unroll
                for (int j = 0; j < TN; j++)
                    acc[i][j] = fmaf(a[i], b[j], acc[i][j]);
        }
        __syncthreads();
    }
    float bv[TN];
    #pragma unroll
    for (int j = 0; j < TN; j++) bv[j] = bias[block_col + tc * TN + j];
    #pragma unroll
    for (int i = 0; i < TM; i++) {
        int gm = block_row + tr * TM + i;
        if (gm >= M) continue;
        #pragma unroll
        for (int j = 0; j < TN; j += 4) {
            float4 v = make_float4(fmaxf(acc[i][j    ] + bv[j    ], 0.0f),
                                   fmaxf(acc[i][j + 1] + bv[j + 1], 0.0f),
                                   fmaxf(acc[i][j + 2] + bv[j + 2], 0.0f),
                                   fmaxf(acc[i][j + 3] + bv[j + 3], 0.0f));
            *((float4*)(C + (size_t)gm * Ncols + block_col + tc * TN + j)) = v;
        }
    }
}

// ---------------- mean pool (batch is sorted) ----------------
#define POOL_CHUNK 64
__global__ void k_pool(const float* __restrict__ h, const int* __restrict__ batch, int N) {
    int f  = threadIdx.x;
    int n0 = blockIdx.x * POOL_CHUNK;
    if (n0 >= N) return;
    int n1 = min(n0 + POOL_CHUNK, N);
    int gcur = batch[n0];
    float acc = 0.0f;
    int c = 0;
    for (int n = n0; n < n1; n++) {
        int g = batch[n];
        if (g != gcur) {
            atomicAdd(&g_sums[gcur * HDIM + f], acc);
            if (f == 0) atomicAdd(&g_gcnt[gcur], (float)c);
            acc = 0.0f; c = 0; gcur = g;
        }
        acc += h[(size_t)n * HDIM + f];
        c++;
    }
    atomicAdd(&g_sums[gcur * HDIM + f], acc);
    if (f == 0) atomicAdd(&g_gcnt[gcur], (float)c);
}

// ---------------- heads: mu / logvar ----------------
__global__ void k_head(const float* __restrict__ Wmu, const float* __restrict__ bmu,
                       const float* __restrict__ Wlv, const float* __restrict__ blv,
                       float* __restrict__ out, int G) {
    int g = blockIdx.x;
    __shared__ float hg[HDIM];
    float invc = 1.0f / fmaxf(g_gcnt[g], 1.0f);
    for (int i = threadIdx.x; i < HDIM; i += blockDim.x)
        hg[i] = g_sums[g * HDIM + i] * invc;
    __syncthreads();
    int t = threadIdx.x;            // 128 threads: 0-63 mu, 64-127 logvar
    const float* W = (t < LDIM) ? Wmu : Wlv;
    const float* b = (t < LDIM) ? bmu : blv;
    int c = t & (LDIM - 1);
    float acc = b[c];
    #pragma unroll 8
    for (int k = 0; k < HDIM; k++)
        acc = fmaf(hg[k], W[k * LDIM + c], acc);
    float* o = (t < LDIM) ? out : (out + (size_t)G * LDIM);
    o[g * LDIM + c] = acc;
}

// ---------------- launch ----------------
extern "C" void kernel_launch(void* const* d_in, const int* in_sizes, int n_in,
                              void* d_out, int out_size) {
    // Resolve inputs in metadata order, skipping the scalar num_graphs (size 1)
    const void* arr[11];
    int arr_sz[11];
    int na = 0;
    for (int i = 0; i < n_in && na < 11; i++) {
        if (in_sizes[i] == 1) continue;
        arr[na] = d_in[i];
        arr_sz[na] = in_sizes[i];
        na++;
    }
    const float* x     = (const float*)arr[0];
    const int*   edge  = (const int*)  arr[1];
    const int*   batch = (const int*)  arr[2];
    const float* W1    = (const float*)arr[3];
    const float* b1    = (const float*)arr[4];
    const float* W2    = (const float*)arr[5];
    const float* b2    = (const float*)arr[6];
    const float* Wmu   = (const float*)arr[7];
    const float* bmu   = (const float*)arr[8];
    const float* Wlv   = (const float*)arr[9];
    const float* blv   = (const float*)arr[10];

    const int N = arr_sz[2];          // batch has N elements
    const int E = arr_sz[1] / 2;      // edge_index is [2, E]
    const int G = NGRAPH;

    const int* src = edge;
    const int* dst = edge + E;

    void* p;
    cudaGetSymbolAddress(&p, g_bufA);   float* bufA = (float*)p;
    cudaGetSymbolAddress(&p, g_bufB);   float* bufB = (float*)p;
    void* p_counts; cudaGetSymbolAddress(&p_counts, g_counts);
    void* p_sums;   cudaGetSymbolAddress(&p_sums,   g_sums);
    void* p_gcnt;   cudaGetSymbolAddress(&p_gcnt,   g_gcnt);

    float* out = (float*)d_out;

    // 1. degree counts + dinv + CSR (+ per-edge weights)
    cudaMemsetAsync(p_counts, 0, (size_t)N * sizeof(int));
    k_count<<<(E + 255) / 256, 256>>>(dst, E);
    k_dinv<<<(N + 255) / 256, 256>>>(N);
    k_scan<<<1, 1024>>>(N, E);
    k_fill<<<(E + 255) / 256, 256>>>(src, dst, E);

    // 2. layer 1: a = Agg(x) [N,128]; h1 = relu(a @ W1 + b1)  (agg commutes with W)
    {
        int warps_per_block = 4;  // 128 threads
        int blocks = (N + warps_per_block - 1) / warps_per_block;
        k_agg<1><<<blocks, warps_per_block * 32>>>(x, bufA, N);
    }
    {
        dim3 grid((HDIM + BN - 1) / BN, (N + BM - 1) / BM);
        k_sgemm_bias_relu<<<grid, 256>>>(bufA, W1, b1, bufB, N, FDIM, HDIM);
    }

    // 3. layer 2: a = Agg(h1) [N,256]; h2 = relu(a @ W2 + b2)
    {
        int warps_per_block = 4;
        int blocks = (N + warps_per_block - 1) / warps_per_block;
        k_agg<2><<<blocks, warps_per_block * 32>>>(bufB, bufA, N);
    }
    {
        dim3 grid((HDIM + BN - 1) / BN, (N + BM - 1) / BM);
        k_sgemm_bias_relu<<<grid, 256>>>(bufA, W2, b2, bufB, N, HDIM, HDIM);
    }

    // 4. mean pool
    cudaMemsetAsync(p_sums, 0, (size_t)G * HDIM * sizeof(float));
    cudaMemsetAsync(p_gcnt, 0, (size_t)G * sizeof(float));
    k_pool<<<(N + POOL_CHUNK - 1) / POOL_CHUNK, 256>>>(bufB, batch, N);

    // 5. heads
    k_head<<<G, 128>>>(Wmu, bmu, Wlv, blv, out, G);
}